// round 1
// baseline (speedup 1.0000x reference)
#include <cuda_runtime.h>
#include <math.h>

// Problem shape (fixed by reference setup_inputs)
#define BB 16
#define CC 8
#define HH 512
#define WW 512
#define NT 64
#define HWSZ (HH * WW)          // 262144
#define HW4  (HWSZ / 4)         // 65536 float4 per channel per batch

// ---- accumulators (device globals: no allocations allowed) ----
__device__ double g_cls_sum;    // sum of softplus(x) over all B*H*W cls cells
__device__ float  g_xmask_sum;  // sum of x at masked cells (cls correction)
__device__ float  g_reg_sum;    // sum of smooth-L1 at masked cells
__device__ int    g_num;        // number of unique masked cells

__global__ void dl_reset_k() {
    g_cls_sum   = 0.0;
    g_xmask_sum = 0.0f;
    g_reg_sum   = 0.0f;
    g_num       = 0;
}

// Sum softplus over channel 0 only. preds layout (B, C, H, W) f32.
// Linear float4 index g in [0, B*HW4): b = g>>16, off = g & 65535.
// Channel-0 float4 address = b * (C*HW4) + off.
__global__ __launch_bounds__(256) void dl_softplus_k(const float4* __restrict__ p4) {
    int g   = blockIdx.x * blockDim.x + threadIdx.x;   // 0 .. 16*65536-1 exactly
    int b   = g >> 16;
    int off = g & 65535;
    float4 v = p4[(size_t)b * (CC * HW4) + off];

    float s = 0.0f;
    {
        float x;
        x = v.x; s += fmaxf(x, 0.0f) + log1pf(expf(-fabsf(x)));
        x = v.y; s += fmaxf(x, 0.0f) + log1pf(expf(-fabsf(x)));
        x = v.z; s += fmaxf(x, 0.0f) + log1pf(expf(-fabsf(x)));
        x = v.w; s += fmaxf(x, 0.0f) + log1pf(expf(-fabsf(x)));
    }

    // warp reduce
    #pragma unroll
    for (int o = 16; o > 0; o >>= 1) s += __shfl_down_sync(0xffffffffu, s, o);

    __shared__ float sh[8];
    int lane = threadIdx.x & 31;
    int w    = threadIdx.x >> 5;
    if (lane == 0) sh[w] = s;
    __syncthreads();
    if (w == 0) {
        s = (lane < 8) ? sh[lane] : 0.0f;
        #pragma unroll
        for (int o = 4; o > 0; o >>= 1) s += __shfl_down_sync(0xffffffffu, s, o);
        if (lane == 0) atomicAdd(&g_cls_sum, (double)s);
    }
}

// One block, 1024 threads = B*NT targets. Dedupe cells per batch in smem
// (last target index wins), then gather cls correction + smooth-L1 terms.
__global__ __launch_bounds__(1024) void dl_targets_k(const float* __restrict__ preds,
                                                     const float* __restrict__ tg) {
    int t = threadIdx.x;            // 0..1023
    int b = t >> 6;                 // batch
    // target vector
    const float* tp = tg + (size_t)t * 7;
    float tv[7];
    #pragma unroll
    for (int c = 0; c < 7; c++) tv[c] = tp[c];

    const float sc = 512.0f / 80.0f;  // f32(6.4), same rounding as JAX scalar
    int gx = (int)fminf(fmaxf(tv[0] * sc, 0.0f), 511.0f);
    int gy = (int)fminf(fmaxf(tv[1] * sc, 0.0f), 511.0f);
    int cell = (b << 18) | (gy << 9) | gx;

    __shared__ int s_cell[1024];
    s_cell[t] = cell;
    __syncthreads();

    // winner = no later target in the same batch hits the same cell
    bool win = true;
    int end = (b << 6) + NT;
    for (int j = t + 1; j < end; j++) {
        if (s_cell[j] == cell) { win = false; break; }
    }

    if (win) {
        size_t base = (size_t)b * CC * HWSZ + (size_t)gy * WW + gx;
        float x = preds[base];                         // cls channel
        float rs = 0.0f;
        #pragma unroll
        for (int c = 0; c < 7; c++) {
            float d  = preds[base + (size_t)(c + 1) * HWSZ] - tv[c];
            float ad = fabsf(d);
            rs += (ad < 1.0f) ? 0.5f * d * d : ad - 0.5f;
        }
        atomicAdd(&g_xmask_sum, x);
        atomicAdd(&g_reg_sum, rs);
        atomicAdd(&g_num, 1);
    }
}

__global__ void dl_final_k(float* __restrict__ out, int out_size) {
    float num = (float)g_num;
    float cls = (float)((g_cls_sum - (double)g_xmask_sum) / (double)((size_t)BB * HWSZ));
    float reg = (num > 0.0f) ? (g_reg_sum / (num + 1e-6f)) : 0.0f;
    float total = cls + 2.0f * reg;
    out[0] = total;
    if (out_size > 1) out[1] = num;
}

extern "C" void kernel_launch(void* const* d_in, const int* in_sizes, int n_in,
                              void* d_out, int out_size) {
    const float* preds   = (const float*)d_in[0];   // (16,8,512,512) f32
    const float* targets = (const float*)d_in[1];   // (16,64,7)     f32
    float* out = (float*)d_out;

    dl_reset_k<<<1, 1>>>();
    // B*HW4 = 16*65536 = 1,048,576 threads -> 4096 blocks of 256
    dl_softplus_k<<<(BB * HW4) / 256, 256>>>((const float4*)preds);
    dl_targets_k<<<1, BB * NT>>>(preds, targets);
    dl_final_k<<<1, 1>>>(out, out_size);

    (void)in_sizes; (void)n_in;
}

// round 2
// speedup vs baseline: 1.0097x; 1.0097x over previous
#include <cuda_runtime.h>
#include <math.h>

// Problem shape (fixed by reference setup_inputs)
#define BB 16
#define CC 8
#define HH 512
#define WW 512
#define NT 64
#define HWSZ (HH * WW)          // 262144
#define HW4  (HWSZ / 4)         // 65536 float4 per channel per batch

#define SP_BLOCKS 128           // softplus blocks (1..128), block 0 = targets
#define NBLOCKS  (SP_BLOCKS + 1)
#define NTHREADS 1024
#define F4_PER_THREAD 8         // 128 blocks * 1024 thr * 8 = 1,048,576 float4 exactly

// ---- accumulators (device globals: zero-initialized; finalize resets them) ----
__device__ double       g_cls_sum;    // sum softplus(x) over all B*H*W cls cells
__device__ float        g_xmask_sum;  // sum of x at masked cells (cls correction)
__device__ float        g_reg_sum;    // sum of smooth-L1 at masked cells
__device__ int          g_num;        // number of unique masked cells
__device__ unsigned int g_done;       // block completion counter

__device__ __forceinline__ float softplus_fast(float x) {
    // max(x,0) + log1p(exp(-|x|)) with fast-math intrinsics (MUFU ex2 + lg2)
    float t = __expf(-fabsf(x));
    return fmaxf(x, 0.0f) + __logf(1.0f + t);
}

__global__ __launch_bounds__(NTHREADS)
void dl_fused_k(const float* __restrict__ preds,
                const float* __restrict__ tg,
                float* __restrict__ out, int out_size) {
    const int tid = threadIdx.x;

    if (blockIdx.x != 0) {
        // ---------- softplus partial sum over channel 0 ----------
        const float4* __restrict__ p4 = (const float4*)preds;
        const int chunk = blockIdx.x - 1;                    // 0..127
        float s = 0.0f;
        #pragma unroll
        for (int k = 0; k < F4_PER_THREAD; k++) {
            int g   = chunk * (NTHREADS * F4_PER_THREAD) + k * NTHREADS + tid;
            int b   = g >> 16;                               // batch
            int off = g & 65535;                             // float4 within H*W
            float4 v = p4[(size_t)b * (CC * HW4) + off];
            s += softplus_fast(v.x) + softplus_fast(v.y)
               + softplus_fast(v.z) + softplus_fast(v.w);
        }
        // warp reduce
        #pragma unroll
        for (int o = 16; o > 0; o >>= 1) s += __shfl_down_sync(0xffffffffu, s, o);
        __shared__ float sh[32];
        int lane = tid & 31, w = tid >> 5;
        if (lane == 0) sh[w] = s;
        __syncthreads();
        if (w == 0) {
            s = sh[lane];
            #pragma unroll
            for (int o = 16; o > 0; o >>= 1) s += __shfl_down_sync(0xffffffffu, s, o);
            if (lane == 0) atomicAdd(&g_cls_sum, (double)s);
        }
    } else {
        // ---------- targets block: dedupe + gather (1024 threads = B*NT) ----------
        const int t = tid;                  // target id 0..1023
        const int b = t >> 6;               // batch
        const float* tp = tg + (size_t)t * 7;
        float tv[7];
        #pragma unroll
        for (int c = 0; c < 7; c++) tv[c] = tp[c];

        const float sc = 512.0f / 80.0f;    // f32(6.4), matches JAX scalar rounding
        int gx = (int)fminf(fmaxf(tv[0] * sc, 0.0f), 511.0f);
        int gy = (int)fminf(fmaxf(tv[1] * sc, 0.0f), 511.0f);
        int cell = (b << 18) | (gy << 9) | gx;

        __shared__ int s_cell[NTHREADS];
        s_cell[t] = cell;
        __syncthreads();

        // winner = no later target in same batch writes the same cell
        bool win = true;
        int end = (b << 6) + NT;
        for (int j = t + 1; j < end; j++)
            if (s_cell[j] == cell) { win = false; break; }

        if (win) {
            size_t base = (size_t)b * CC * HWSZ + (size_t)gy * WW + gx;
            float x = preds[base];                        // cls channel
            float rs = 0.0f;
            #pragma unroll
            for (int c = 0; c < 7; c++) {
                float d  = preds[base + (size_t)(c + 1) * HWSZ] - tv[c];
                float ad = fabsf(d);
                rs += (ad < 1.0f) ? 0.5f * d * d : ad - 0.5f;
            }
            atomicAdd(&g_xmask_sum, x);
            atomicAdd(&g_reg_sum, rs);
            atomicAdd(&g_num, 1);
        }
    }

    // ---------- last-block finalize ----------
    __threadfence();
    __shared__ bool s_last;
    if (tid == 0)
        s_last = (atomicAdd(&g_done, 1u) == (unsigned)(NBLOCKS - 1));
    __syncthreads();
    if (s_last && tid == 0) {
        float num = (float)g_num;
        float cls = (float)((g_cls_sum - (double)g_xmask_sum) /
                            (double)((size_t)BB * HWSZ));
        float reg = (num > 0.0f) ? (g_reg_sum / (num + 1e-6f)) : 0.0f;
        out[0] = cls + 2.0f * reg;
        if (out_size > 1) out[1] = num;
        // reset for next graph replay (deterministic across launches)
        g_cls_sum   = 0.0;
        g_xmask_sum = 0.0f;
        g_reg_sum   = 0.0f;
        g_num       = 0;
        __threadfence();
        g_done      = 0u;
    }
}

extern "C" void kernel_launch(void* const* d_in, const int* in_sizes, int n_in,
                              void* d_out, int out_size) {
    const float* preds   = (const float*)d_in[0];   // (16,8,512,512) f32
    const float* targets = (const float*)d_in[1];   // (16,64,7)     f32
    float* out = (float*)d_out;

    dl_fused_k<<<NBLOCKS, NTHREADS>>>(preds, targets, out, out_size);

    (void)in_sizes; (void)n_in;
}